// round 6
// baseline (speedup 1.0000x reference)
#include <cuda_runtime.h>

// LSTM_model_59244778881379 — autoregressive LSTM rollout, persistent per-CTA.
// B=8192, T=64, F=64, ORDER=16, K=256. fp32 (fma.rn.f32x2 packed FMA).
//
// R4 change vs R0: occupancy 1 -> 2 CTAs/SM (4 warps/SMSP) to hide L2 weight-load
// latency. MROWS 32 -> 16, thread tile 8x4 -> 4x4 (acc 128 -> 64 regs), bias and
// dense_w moved to SMEM, __launch_bounds__(256, 2) (<=128 regs/thread).

#define BATCH    8192
#define HOR      64
#define FDIM     64
#define ORD      16
#define KH       256
#define INPD     (FDIM + ORD + KH)   /* 336 */
#define GATE4    1024
#define MROWS    16
#define NTHREADS 256

__device__ __forceinline__ unsigned long long ffma2(unsigned long long a,
                                                    unsigned long long b,
                                                    unsigned long long c) {
    unsigned long long d;
    asm("fma.rn.f32x2 %0, %1, %2, %3;" : "=l"(d) : "l"(a), "l"(b), "l"(c));
    return d;
}
__device__ __forceinline__ unsigned long long pack2(float x) {
    unsigned long long d;
    asm("mov.b64 %0, {%1, %1};" : "=l"(d) : "f"(x));
    return d;
}
__device__ __forceinline__ unsigned long long pk2(float a, float b) {
    unsigned long long d;
    asm("mov.b64 %0, {%1, %2};" : "=l"(d) : "f"(a), "f"(b));
    return d;
}
__device__ __forceinline__ float2 upk(unsigned long long v) {
    float2 r;
    asm("mov.b64 {%0, %1}, %2;" : "=f"(r.x), "=f"(r.y) : "l"(v));
    return r;
}

union F4U { float4 v; unsigned long long u[2]; };

__device__ __forceinline__ float sigmoidf_(float x) {
    return 1.0f / (1.0f + __expf(-x));
}

// One 4-wide K chunk: acc[g][r][pair] += inp[r0+r][coloff+k] * W[k][g*256+u0..+3]
__device__ __forceinline__ void gemm_chunk(
    unsigned long long (&acc)[4][4][2],
    const float (&inp)[MROWS][INPD],
    const float* __restrict__ wbase,
    int kc, int coloff, int r0, int u0)
{
    float av[4][4];
#pragma unroll
    for (int r = 0; r < 4; r++) {
        float4 tv = *(const float4*)&inp[r0 + r][coloff + kc];
        av[r][0] = tv.x; av[r][1] = tv.y; av[r][2] = tv.z; av[r][3] = tv.w;
    }
#pragma unroll
    for (int kk = 0; kk < 4; kk++) {
        const float* wrow = wbase + (size_t)(kc + kk) * GATE4 + u0;
        F4U w[4];
#pragma unroll
        for (int g = 0; g < 4; g++)
            w[g].v = __ldg((const float4*)(wrow + g * KH));
#pragma unroll
        for (int r = 0; r < 4; r++) {
            unsigned long long a2 = pack2(av[r][kk]);
#pragma unroll
            for (int g = 0; g < 4; g++) {
                acc[g][r][0] = ffma2(a2, w[g].u[0], acc[g][r][0]);
                acc[g][r][1] = ffma2(a2, w[g].u[1], acc[g][r][1]);
            }
        }
    }
}

__global__ void __launch_bounds__(NTHREADS, 2)
lstm_rollout(const float* __restrict__ x, const float* __restrict__ y0,
             const float* __restrict__ Wk, const float* __restrict__ Wr,
             const float* __restrict__ bias, const float* __restrict__ dw,
             const float* __restrict__ db, float* __restrict__ out)
{
    __shared__ __align__(16) float inp_s[MROWS][INPD]; // [x(64)|yp(16)|h(256)]
    __shared__ __align__(16) float ypb[MROWS][ORD];    // circular yp buffer
    __shared__ __align__(16) float bias_s[GATE4];
    __shared__ __align__(16) float dw_s[KH];
    __shared__ float db_s;

    const int tid  = threadIdx.x;
    const int rg   = tid >> 6;        // 0..3  (row group: 4 rows each)
    const int ug   = tid & 63;        // 0..63 (unit group: 4 units each)
    const int r0   = rg * 4;
    const int u0   = ug * 4;
    const int row0 = blockIdx.x * MROWS;

    // h0 = 0
    for (int i = tid; i < MROWS * KH; i += NTHREADS)
        inp_s[i >> 8][FDIM + ORD + (i & 255)] = 0.0f;
    // yp circular buffer <- y0 (head = 0: yp[j] = ypb[(head+j)&15])
    {
        int r = tid >> 4, j = tid & 15;
        ypb[r][j] = __ldg(y0 + (size_t)(row0 + r) * ORD + j);
    }
    // bias, dense_w, dense_b -> smem
    for (int i = tid; i < GATE4; i += NTHREADS) bias_s[i] = __ldg(bias + i);
    if (tid < KH) dw_s[tid] = __ldg(dw + tid);
    if (tid == 0) db_s = __ldg(db);

    // c state (4 rows x 4 units) packed
    unsigned long long c2[4][2];
#pragma unroll
    for (int r = 0; r < 4; r++) { c2[r][0] = 0ull; c2[r][1] = 0ull; }

    int head = 0;
    __syncthreads();

    for (int t = 0; t < HOR; t++) {
        // ---- stage x_t and ordered yp window ----
        {
            int r = tid >> 4, f4 = tid & 15;   // 16 rows x 16 float4
            float4 xv = __ldg((const float4*)(x + ((size_t)(row0 + r) * HOR + t) * FDIM + f4 * 4));
            *(float4*)&inp_s[r][f4 * 4] = xv;
            int jr = tid >> 4, j = tid & 15;
            inp_s[jr][FDIM + j] = ypb[jr][(head + j) & 15];
        }
        __syncthreads();

        // ---- fused GEMM: z = [x|yp] @ Wk + h @ Wr + bias ----
        unsigned long long acc[4][4][2];
#pragma unroll
        for (int g = 0; g < 4; g++) {
            F4U b; b.v = *(const float4*)&bias_s[g * KH + u0];
#pragma unroll
            for (int r = 0; r < 4; r++) {
                acc[g][r][0] = b.u[0];
                acc[g][r][1] = b.u[1];
            }
        }

#pragma unroll 1
        for (int kc = 0; kc < FDIM + ORD; kc += 4)
            gemm_chunk(acc, inp_s, Wk, kc, 0, r0, u0);
#pragma unroll 1
        for (int kc = 0; kc < KH; kc += 4)
            gemm_chunk(acc, inp_s, Wr, kc, FDIM + ORD, r0, u0);

        // ---- gates + state update (thread-local) ----
        float hv[4][4];
#pragma unroll
        for (int r = 0; r < 4; r++) {
#pragma unroll
            for (int p = 0; p < 2; p++) {
                float2 iv = upk(acc[0][r][p]);
                float2 fv = upk(acc[1][r][p]);
                float2 gv = upk(acc[2][r][p]);
                float2 ov = upk(acc[3][r][p]);
                float2 cc = upk(c2[r][p]);
                float i0 = sigmoidf_(iv.x), i1 = sigmoidf_(iv.y);
                float f0 = sigmoidf_(fv.x), f1 = sigmoidf_(fv.y);
                float g0 = tanhf(gv.x),     g1 = tanhf(gv.y);
                float o0 = sigmoidf_(ov.x), o1 = sigmoidf_(ov.y);
                float cn0 = f0 * cc.x + i0 * g0;
                float cn1 = f1 * cc.y + i1 * g1;
                c2[r][p] = pk2(cn0, cn1);
                hv[r][2 * p + 0] = o0 * tanhf(cn0);
                hv[r][2 * p + 1] = o1 * tanhf(cn1);
            }
        }

        __syncthreads();   // all GEMM reads of inp_s done before h overwrite
#pragma unroll
        for (int r = 0; r < 4; r++)
            *(float4*)&inp_s[r0 + r][FDIM + ORD + u0] =
                make_float4(hv[r][0], hv[r][1], hv[r][2], hv[r][3]);
        __syncthreads();   // h_t fully visible

        // ---- pred = h @ dense_w + db ; shift into yp window ----
        {
            int r = tid >> 4, j = tid & 15;   // 16 rows x 16 lanes
            float s = 0.f;
#pragma unroll
            for (int u = j; u < KH; u += 16)
                s += inp_s[r][FDIM + ORD + u] * dw_s[u];
            s += __shfl_down_sync(0xffffffffu, s, 8, 16);
            s += __shfl_down_sync(0xffffffffu, s, 4, 16);
            s += __shfl_down_sync(0xffffffffu, s, 2, 16);
            s += __shfl_down_sync(0xffffffffu, s, 1, 16);
            if (j == 0) {
                float p = s + db_s;
                out[(size_t)(row0 + r) * HOR + t] = p;
                ypb[r][(head + 15) & 15] = p;   // new head slot
            }
        }
        head = (head + 15) & 15;   // head -= 1 (mod 16), uniform
        __syncthreads();           // ypb write visible before next staging
    }
}

extern "C" void kernel_launch(void* const* d_in, const int* in_sizes, int n_in,
                              void* d_out, int out_size) {
    const float* x    = (const float*)d_in[0];
    const float* y0   = (const float*)d_in[1];
    const float* Wk   = (const float*)d_in[2];   // [80, 1024]
    const float* Wr   = (const float*)d_in[3];   // [256, 1024]
    const float* bias = (const float*)d_in[4];   // [1024]
    const float* dw   = (const float*)d_in[5];   // [256, 1]
    const float* db   = (const float*)d_in[6];   // [1]
    float* out = (float*)d_out;                  // [8192, 64, 1]
    lstm_rollout<<<BATCH / MROWS, NTHREADS>>>(x, y0, Wk, Wr, bias, dw, db, out);
}

// round 8
// speedup vs baseline: 1.1041x; 1.1041x over previous
#include <cuda_runtime.h>

// LSTM_model_59244778881379 — autoregressive LSTM rollout, persistent per-CTA.
// B=8192, T=64, F=64, ORDER=16, K=256. fp32 (fma.rn.f32x2 packed FMA).
//
// R6 (resubmitted R7 after infra flake): R0 shape (MROWS=32, 8x4 tile, 1 CTA/SM)
// + software-pipelined weight prefetch: per-k GEMM with a 3-deep register ring
// of weight float4s (loads issued 2 k-rows ahead -> L2 latency hidden under FMA
// issue). A-operand comes from SMEM broadcast LDS per k (warp lanes share row
// group).

#define BATCH    8192
#define HOR      64
#define FDIM     64
#define ORD      16
#define KH       256
#define INPD     (FDIM + ORD + KH)   /* 336 */
#define KTOT     INPD
#define KSPLIT   (FDIM + ORD)        /* 80: Wk rows before Wr */
#define GATE4    1024
#define MROWS    32
#define NTHREADS 256

typedef unsigned long long u64;

__device__ __forceinline__ u64 ffma2(u64 a, u64 b, u64 c) {
    u64 d;
    asm("fma.rn.f32x2 %0, %1, %2, %3;" : "=l"(d) : "l"(a), "l"(b), "l"(c));
    return d;
}
__device__ __forceinline__ u64 pack2(float x) {
    u64 d;
    asm("mov.b64 %0, {%1, %1};" : "=l"(d) : "f"(x));
    return d;
}
__device__ __forceinline__ u64 pk2(float a, float b) {
    u64 d;
    asm("mov.b64 %0, {%1, %2};" : "=l"(d) : "f"(a), "f"(b));
    return d;
}
__device__ __forceinline__ float2 upk(u64 v) {
    float2 r;
    asm("mov.b64 {%0, %1}, %2;" : "=f"(r.x), "=f"(r.y) : "l"(v));
    return r;
}

union F4U { float4 v; u64 u[2]; };

struct WB { u64 u[8]; };   // 4 gates x float4 = 16 floats

__device__ __forceinline__ float sigmoidf_(float x) {
    return 1.0f / (1.0f + __expf(-x));
}

// Load weight row k (concatenated [Wk;Wr]) for this thread's 4 units x 4 gates.
__device__ __forceinline__ void loadw(WB& w, const float* __restrict__ Wk,
                                      const float* __restrict__ Wr, int k, int u0) {
    const float* wr = (k < KSPLIT) ? (Wk + (size_t)k * GATE4 + u0)
                                   : (Wr + (size_t)(k - KSPLIT) * GATE4 + u0);
#pragma unroll
    for (int g = 0; g < 4; g++) {
        F4U t; t.v = __ldg((const float4*)(wr + g * KH));
        w.u[2 * g + 0] = t.u[0];
        w.u[2 * g + 1] = t.u[1];
    }
}

// One k-row of the fused GEMM: acc[g][r] += inp[r0+r][k] * W[k][g*256+u0..u0+3]
__device__ __forceinline__ void fmak(u64 (&acc)[4][8][2], const WB& w,
                                     const float (&inp)[MROWS][INPD],
                                     int k, int r0) {
#pragma unroll
    for (int r = 0; r < 8; r++) {
        u64 a2 = pack2(inp[r0 + r][k]);   // LDS broadcast (lanes share r0)
#pragma unroll
        for (int g = 0; g < 4; g++) {
            acc[g][r][0] = ffma2(a2, w.u[2 * g + 0], acc[g][r][0]);
            acc[g][r][1] = ffma2(a2, w.u[2 * g + 1], acc[g][r][1]);
        }
    }
}

__global__ void __launch_bounds__(NTHREADS, 1)
lstm_rollout(const float* __restrict__ x, const float* __restrict__ y0,
             const float* __restrict__ Wk, const float* __restrict__ Wr,
             const float* __restrict__ bias, const float* __restrict__ dw,
             const float* __restrict__ db, float* __restrict__ out)
{
    __shared__ __align__(16) float inp_s[MROWS][INPD]; // [x(64)|yp(16)|h(256)]
    __shared__ __align__(16) float ypb[MROWS][ORD];    // circular yp buffer
    __shared__ __align__(16) float bias_s[GATE4];
    __shared__ __align__(16) float dw_s[KH];
    __shared__ float db_s;

    const int tid  = threadIdx.x;
    const int r0   = (tid >> 6) * 8;   // row group: 8 rows
    const int u0   = (tid & 63) * 4;   // unit group: 4 units
    const int row0 = blockIdx.x * MROWS;

    // h0 = 0
    for (int i = tid; i < MROWS * KH; i += NTHREADS)
        inp_s[i >> 8][FDIM + ORD + (i & 255)] = 0.0f;
    // yp circular buffer <- y0 (head = 0: yp[j] = ypb[(head+j)&15])
    for (int i = tid; i < MROWS * ORD; i += NTHREADS) {
        int r = i >> 4, j = i & 15;
        ypb[r][j] = __ldg(y0 + (size_t)(row0 + r) * ORD + j);
    }
    // bias, dense weights -> smem
    for (int i = tid; i < GATE4; i += NTHREADS) bias_s[i] = __ldg(bias + i);
    if (tid < KH) dw_s[tid] = __ldg(dw + tid);
    if (tid == 0) db_s = __ldg(db);

    // c state (8 rows x 4 units) packed
    u64 c2[8][2];
#pragma unroll
    for (int r = 0; r < 8; r++) { c2[r][0] = 0ull; c2[r][1] = 0ull; }

    int head = 0;
    __syncthreads();

    for (int t = 0; t < HOR; t++) {
        // ---- stage x_t and ordered yp window into inp_s ----
        for (int i = tid; i < MROWS * (FDIM / 4); i += NTHREADS) {
            int r = i >> 4, f4 = i & 15;
            float4 xv = __ldg((const float4*)(x + ((size_t)(row0 + r) * HOR + t) * FDIM + f4 * 4));
            *(float4*)&inp_s[r][f4 * 4] = xv;
        }
        for (int i = tid; i < MROWS * ORD; i += NTHREADS) {
            int r = i >> 4, j = i & 15;
            inp_s[r][FDIM + j] = ypb[r][(head + j) & 15];
        }
        __syncthreads();

        // ---- acc <- bias ----
        u64 acc[4][8][2];
#pragma unroll
        for (int g = 0; g < 4; g++) {
            F4U b; b.v = *(const float4*)&bias_s[g * KH + u0];
#pragma unroll
            for (int r = 0; r < 8; r++) {
                acc[g][r][0] = b.u[0];
                acc[g][r][1] = b.u[1];
            }
        }

        // ---- fused GEMM, per-k with 3-deep weight prefetch ring ----
        WB wb0, wb1, wb2;
        loadw(wb0, Wk, Wr, 0, u0);
        loadw(wb1, Wk, Wr, 1, u0);
#pragma unroll 1
        for (int k = 0; k < KTOT; k += 3) {            // 336 = 3*112
            loadw(wb2, Wk, Wr, k + 2, u0);             // k+2 < 336 always
            fmak(acc, wb0, inp_s, k, r0);
            if (k + 3 < KTOT) loadw(wb0, Wk, Wr, k + 3, u0);
            fmak(acc, wb1, inp_s, k + 1, r0);
            if (k + 4 < KTOT) loadw(wb1, Wk, Wr, k + 4, u0);
            fmak(acc, wb2, inp_s, k + 2, r0);
        }

        // ---- gates + state update (thread-local) ----
        float hv[8][4];
#pragma unroll
        for (int r = 0; r < 8; r++) {
#pragma unroll
            for (int p = 0; p < 2; p++) {
                float2 iv = upk(acc[0][r][p]);
                float2 fv = upk(acc[1][r][p]);
                float2 gv = upk(acc[2][r][p]);
                float2 ov = upk(acc[3][r][p]);
                float2 cc = upk(c2[r][p]);
                float i0 = sigmoidf_(iv.x), i1 = sigmoidf_(iv.y);
                float f0 = sigmoidf_(fv.x), f1 = sigmoidf_(fv.y);
                float g0 = tanhf(gv.x),     g1 = tanhf(gv.y);
                float o0 = sigmoidf_(ov.x), o1 = sigmoidf_(ov.y);
                float cn0 = f0 * cc.x + i0 * g0;
                float cn1 = f1 * cc.y + i1 * g1;
                c2[r][p] = pk2(cn0, cn1);
                hv[r][2 * p + 0] = o0 * tanhf(cn0);
                hv[r][2 * p + 1] = o1 * tanhf(cn1);
            }
        }

        __syncthreads();   // all GEMM reads of inp_s done before h overwrite
#pragma unroll
        for (int r = 0; r < 8; r++)
            *(float4*)&inp_s[r0 + r][FDIM + ORD + u0] =
                make_float4(hv[r][0], hv[r][1], hv[r][2], hv[r][3]);
        __syncthreads();   // h_t fully visible

        // ---- pred = h @ dense_w + db ; shift into yp window ----
        {
            int r = tid >> 3, j = tid & 7;   // 32 rows x 8 lanes
            float s = 0.f;
#pragma unroll
            for (int u = j; u < KH; u += 8)
                s += inp_s[r][FDIM + ORD + u] * dw_s[u];
            s += __shfl_down_sync(0xffffffffu, s, 4, 8);
            s += __shfl_down_sync(0xffffffffu, s, 2, 8);
            s += __shfl_down_sync(0xffffffffu, s, 1, 8);
            if (j == 0) {
                float p = s + db_s;
                out[(size_t)(row0 + r) * HOR + t] = p;
                ypb[r][(head + 15) & 15] = p;   // new head slot
            }
        }
        head = (head + 15) & 15;   // head -= 1 (mod 16), uniform
        __syncthreads();           // ypb write visible before next staging
    }
}

extern "C" void kernel_launch(void* const* d_in, const int* in_sizes, int n_in,
                              void* d_out, int out_size) {
    const float* x    = (const float*)d_in[0];
    const float* y0   = (const float*)d_in[1];
    const float* Wk   = (const float*)d_in[2];   // [80, 1024]
    const float* Wr   = (const float*)d_in[3];   // [256, 1024]
    const float* bias = (const float*)d_in[4];   // [1024]
    const float* dw   = (const float*)d_in[5];   // [256, 1]
    const float* db   = (const float*)d_in[6];   // [1]
    float* out = (float*)d_out;                  // [8192, 64, 1]
    lstm_rollout<<<BATCH / MROWS, NTHREADS>>>(x, y0, Wk, Wr, bias, dw, db, out);
}